// round 10
// baseline (speedup 1.0000x reference)
#include <cuda_runtime.h>

// Problem constants (fixed by setup_inputs)
#define DD   2048          // D
#define UU   37            // units
#define BB   16            // batch
#define CHUNK 8192         // floats per chunk of the D*D plane
#define NCHUNK ((DD*DD)/CHUNK)   // 512
#define NTHREADS 256
#define F4_PER_THREAD (CHUNK / 4 / NTHREADS)  // 8 float4 per thread

#define NDIAG  (UU * DD)                      // 75776 diagonal elems
#define GBLOCKS (NDIAG / NTHREADS)            // 296 (exact)
#define SLICES_PER_U (DD / NTHREADS)          // 8
#define NDVALS (BB + 1)                       // 17: [acc1, acc2[0..15]]
#define NWORK  (NCHUNK + GBLOCKS)             // 808 = total blocks (all produce)

// Scratch (device globals; no allocation allowed)
__device__ float g_Spart[UU * NCHUNK];            // dense partials [u][chunk]
__device__ float g_diagpart[GBLOCKS * NDVALS];    // diag partials [slice][17]
__device__ unsigned int g_count = 0;              // producer arrivals
__device__ unsigned int g_fin   = 0;              // finalizer arrivals

// Grid layout: [dense 0..511][diag 512..807].
// Wave 1 (592 slots @ 4 CTAs/SM) holds ALL dense blocks, so finalizer
// spin-slots never displace dense work. The diag block with slice%8==7
// also finalizes unit u = slice/8 after all producers arrive.
__global__ void __launch_bounds__(NTHREADS) gfrm_fused_kernel(
    const float* __restrict__ inputs,
    const float* __restrict__ matrix,
    const float* __restrict__ weight,
    const float* __restrict__ bias,
    float* __restrict__ out)
{
    const int tid  = threadIdx.x;
    const int lane = tid & 31;
    const int wid  = tid >> 5;

    __shared__ float sm17[NDVALS][NTHREADS / 32];  // reused across phases

    if (blockIdx.x < NCHUNK) {
        // ---- dense partial stage (register m-cache: MLP needs the regs) ----
        const int c = blockIdx.x;               // chunk id, 0..NCHUNK-1
        const size_t base = (size_t)c * CHUNK;  // float offset into D*D plane

        float4 m[F4_PER_THREAD];
        const float4* mp = reinterpret_cast<const float4*>(matrix + base);
#pragma unroll
        for (int k = 0; k < F4_PER_THREAD; k++) {
            float4 v = mp[k * NTHREADS + tid];
            m[k].x = fmaxf(v.x, 0.0f);
            m[k].y = fmaxf(v.y, 0.0f);
            m[k].z = fmaxf(v.z, 0.0f);
            m[k].w = fmaxf(v.w, 0.0f);
        }

        __shared__ float warp_part[UU][NTHREADS / 32];

        for (int u = 0; u < UU; u++) {
            const float4* wp = reinterpret_cast<const float4*>(
                weight + (size_t)u * DD * DD + base);
            float s0 = 0.f, s1 = 0.f, s2 = 0.f, s3 = 0.f;
#pragma unroll
            for (int k = 0; k < F4_PER_THREAD; k++) {
                float4 w = __ldcs(wp + k * NTHREADS + tid);  // read-once stream
                s0 = fmaf(m[k].x, w.x, s0);
                s1 = fmaf(m[k].y, w.y, s1);
                s2 = fmaf(m[k].z, w.z, s2);
                s3 = fmaf(m[k].w, w.w, s3);
            }
            float s = (s0 + s1) + (s2 + s3);
            // deterministic warp reduce
#pragma unroll
            for (int o = 16; o > 0; o >>= 1)
                s += __shfl_xor_sync(0xffffffffu, s, o);
            if (lane == 0) warp_part[u][wid] = s;
        }
        __syncthreads();

        if (tid < UU) {
            float s = 0.f;
#pragma unroll
            for (int w = 0; w < NTHREADS / 32; w++) s += warp_part[tid][w];
            g_Spart[tid * NCHUNK + c] = s;
        }

        __syncthreads();
        if (tid == 0) {
            __threadfence();
            atomicAdd(&g_count, 1u);
        }
        return;
    }

    // ---- diagonal stage: one block per 256-element slice of one u ----
    const int slice = blockIdx.x - NCHUNK;        // 0..295
    {
        const int g = slice * NTHREADS + tid;     // global diag index
        const int du = g >> 11;                   // constant per block
        const int i = g & (DD - 1);

        const float mii = matrix[(size_t)i * (DD + 1)];
        const float wii = __ldcs(weight + (size_t)du * DD * DD
                                        + (size_t)i * (DD + 1));

        float v[NDVALS];
        v[0] = fmaxf(mii, 0.0f) * wii;            // plain-diag term
#pragma unroll
        for (int b = 0; b < BB; b++) {
            const float x = inputs[b * DD + i];
            v[1 + b] = fmaxf(mii * x, 0.0f) * wii;
        }

        // deterministic warp reduce of all 17 values
#pragma unroll
        for (int k = 0; k < NDVALS; k++) {
#pragma unroll
            for (int o = 16; o > 0; o >>= 1)
                v[k] += __shfl_xor_sync(0xffffffffu, v[k], o);
        }
        if (lane == 0) {
#pragma unroll
            for (int k = 0; k < NDVALS; k++) sm17[k][wid] = v[k];
        }
        __syncthreads();
        if (tid < NDVALS) {
            float s = 0.f;
#pragma unroll
            for (int w = 0; w < NTHREADS / 32; w++) s += sm17[tid][w];
            g_diagpart[slice * NDVALS + tid] = s;
        }
        __syncthreads();
        if (tid == 0) {
            __threadfence();
            atomicAdd(&g_count, 1u);
        }
    }

    // ---- finalize (only the last-slice block of each u) ----
    if ((slice & (SLICES_PER_U - 1)) != SLICES_PER_U - 1) return;
    const int u = slice >> 3;                     // slice / 8

    if (tid == 0) {
        while (atomicAdd(&g_count, 0u) != NWORK) __nanosleep(128);
        __threadfence();   // acquire: order partial reads after counter
    }
    __syncthreads();

    // Reduce 512 dense partials for this u (L2 loads, fixed order).
    float s = __ldcg(&g_Spart[u * NCHUNK + tid])
            + __ldcg(&g_Spart[u * NCHUNK + NTHREADS + tid]);
#pragma unroll
    for (int o = 16; o > 0; o >>= 1)
        s += __shfl_xor_sync(0xffffffffu, s, o);

    __shared__ float ws[NTHREADS / 32];
    __shared__ float diag[NDVALS];
    if (lane == 0) ws[wid] = s;

    if (tid < NDVALS) {
        float d = 0.f;
#pragma unroll
        for (int sl = 0; sl < SLICES_PER_U; sl++)
            d += __ldcg(&g_diagpart[(u * SLICES_PER_U + sl) * NDVALS + tid]);
        diag[tid] = d;
    }
    __syncthreads();

    if (tid < BB) {
        float S = 0.f;
#pragma unroll
        for (int w = 0; w < NTHREADS / 32; w++) S += ws[w];
        out[tid * UU + u] = S - diag[0] + diag[1 + tid] + bias[u];
    }

    // Last finalizer resets counters for the next graph replay.
    __syncthreads();
    if (tid == 0) {
        __threadfence();
        unsigned int prev = atomicAdd(&g_fin, 1u);
        if (prev == UU - 1) {
            g_count = 0;
            g_fin = 0;
        }
    }
}

extern "C" void kernel_launch(void* const* d_in, const int* in_sizes, int n_in,
                              void* d_out, int out_size)
{
    const float* inputs = (const float*)d_in[0];  // (16, 2048)
    const float* matrix = (const float*)d_in[1];  // (2048, 2048)
    const float* weight = (const float*)d_in[2];  // (37, 2048, 2048)
    const float* bias   = (const float*)d_in[3];  // (37,)
    float* out = (float*)d_out;                    // (16, 37)

    gfrm_fused_kernel<<<NWORK, NTHREADS>>>(inputs, matrix, weight, bias, out);
}

// round 11
// speedup vs baseline: 1.0425x; 1.0425x over previous
#include <cuda_runtime.h>

// Problem constants (fixed by setup_inputs)
#define DD   2048          // D
#define UU   37            // units
#define BB   16            // batch
#define CHUNK 8192         // floats per chunk of the D*D plane
#define NCHUNK ((DD*DD)/CHUNK)   // 512
#define NTHREADS 256
#define F4_PER_THREAD (CHUNK / 4 / NTHREADS)  // 8 float4 per thread

#define NDIAG  (UU * DD)                      // 75776 diagonal elems
#define GBLOCKS (NDIAG / NTHREADS)            // 296 (exact)
#define SLICES_PER_U (DD / NTHREADS)          // 8
#define NDVALS (BB + 1)                       // 17: [acc1, acc2[0..15]]

// Scratch (device globals; no allocation allowed)
__device__ float g_Spart[UU * NCHUNK];            // dense partials [u][chunk]
__device__ float g_diagpart[GBLOCKS * NDVALS];    // diag partials [slice][17]

// Kernel 1 (R3 layout — measured ~6.9 TB/s):
//  blocks [0, NCHUNK):        dense contraction partials — weight read once,
//                             relu(matrix) chunk cached in registers (MLP!).
//  blocks [NCHUNK, +GBLOCKS): diagonal-term partial sums (cheap, overlapped).
__global__ void __launch_bounds__(NTHREADS) gfrm_partial_kernel(
    const float* __restrict__ inputs,
    const float* __restrict__ matrix,
    const float* __restrict__ weight)
{
    const int tid  = threadIdx.x;
    const int lane = tid & 31;
    const int wid  = tid >> 5;

    // PDL: signal early so the dependent finalize kernel can launch and
    // overlap its dispatch with our tail. Its grid-sync still waits for
    // our full completion before reading partials.
    if (tid == 0) cudaTriggerProgrammaticLaunchCompletion();

    if (blockIdx.x >= NCHUNK) {
        // ---- diagonal stage: one block per 256-element slice of one u ----
        const int slice = blockIdx.x - NCHUNK;        // 0..295
        const int g = slice * NTHREADS + tid;         // global diag index
        const int u = g >> 11;                        // constant per block
        const int i = g & (DD - 1);

        const float mii = matrix[(size_t)i * (DD + 1)];
        const float wii = __ldcs(weight + (size_t)u * DD * DD
                                        + (size_t)i * (DD + 1));

        float v[NDVALS];
        v[0] = fmaxf(mii, 0.0f) * wii;                // plain-diag term
#pragma unroll
        for (int b = 0; b < BB; b++) {
            const float x = inputs[b * DD + i];
            v[1 + b] = fmaxf(mii * x, 0.0f) * wii;    // batch-diag terms
        }

        // deterministic warp reduce of all 17 values
#pragma unroll
        for (int k = 0; k < NDVALS; k++) {
#pragma unroll
            for (int o = 16; o > 0; o >>= 1)
                v[k] += __shfl_xor_sync(0xffffffffu, v[k], o);
        }
        __shared__ float wp[NDVALS][NTHREADS / 32];
        if (lane == 0) {
#pragma unroll
            for (int k = 0; k < NDVALS; k++) wp[k][wid] = v[k];
        }
        __syncthreads();
        if (tid < NDVALS) {
            float s = 0.f;
#pragma unroll
            for (int w = 0; w < NTHREADS / 32; w++) s += wp[tid][w];
            g_diagpart[slice * NDVALS + tid] = s;
        }
        return;
    }

    // ---- dense partial stage ----
    const int c = blockIdx.x;               // chunk id, 0..NCHUNK-1
    const size_t base = (size_t)c * CHUNK;  // float offset into D*D plane

    // Load + relu the matrix chunk into registers (coalesced float4).
    float4 m[F4_PER_THREAD];
    const float4* mp = reinterpret_cast<const float4*>(matrix + base);
#pragma unroll
    for (int k = 0; k < F4_PER_THREAD; k++) {
        float4 v = mp[k * NTHREADS + tid];
        m[k].x = fmaxf(v.x, 0.0f);
        m[k].y = fmaxf(v.y, 0.0f);
        m[k].z = fmaxf(v.z, 0.0f);
        m[k].w = fmaxf(v.w, 0.0f);
    }

    __shared__ float warp_part[UU][NTHREADS / 32];

    for (int u = 0; u < UU; u++) {
        const float4* wp = reinterpret_cast<const float4*>(
            weight + (size_t)u * DD * DD + base);
        float s0 = 0.f, s1 = 0.f, s2 = 0.f, s3 = 0.f;
#pragma unroll
        for (int k = 0; k < F4_PER_THREAD; k++) {
            float4 w = __ldcs(wp + k * NTHREADS + tid);  // read-once stream
            s0 = fmaf(m[k].x, w.x, s0);
            s1 = fmaf(m[k].y, w.y, s1);
            s2 = fmaf(m[k].z, w.z, s2);
            s3 = fmaf(m[k].w, w.w, s3);
        }
        float s = (s0 + s1) + (s2 + s3);
        // deterministic warp reduce
#pragma unroll
        for (int o = 16; o > 0; o >>= 1)
            s += __shfl_xor_sync(0xffffffffu, s, o);
        if (lane == 0) warp_part[u][wid] = s;
    }
    __syncthreads();

    if (tid < UU) {
        float s = 0.f;
#pragma unroll
        for (int w = 0; w < NTHREADS / 32; w++) s += warp_part[tid][w];
        g_Spart[tid * NCHUNK + c] = s;
    }
}

// Kernel 2 (PDL dependent): launched programmatically; overlaps its dispatch
// with kernel1's tail, then grid-syncs before touching partials.
__global__ void __launch_bounds__(NTHREADS) gfrm_final_kernel(
    const float* __restrict__ bias,
    float* __restrict__ out)
{
    const int u    = blockIdx.x;
    const int tid  = threadIdx.x;
    const int lane = tid & 31;
    const int wid  = tid >> 5;

    // Wait until kernel1's writes are complete and visible.
    cudaGridDependencySynchronize();

    // Reduce 512 dense partials for this u (2 per thread, then tree).
    float s = g_Spart[u * NCHUNK + tid] + g_Spart[u * NCHUNK + NTHREADS + tid];
#pragma unroll
    for (int o = 16; o > 0; o >>= 1)
        s += __shfl_xor_sync(0xffffffffu, s, o);

    __shared__ float ws[NTHREADS / 32];
    __shared__ float diag[NDVALS];
    if (lane == 0) ws[wid] = s;

    // Reduce the 8 diag slice-partials for this u.
    if (tid < NDVALS) {
        float d = 0.f;
#pragma unroll
        for (int sl = 0; sl < SLICES_PER_U; sl++)
            d += g_diagpart[(u * SLICES_PER_U + sl) * NDVALS + tid];
        diag[tid] = d;
    }
    __syncthreads();

    if (tid < BB) {
        float S = 0.f;
#pragma unroll
        for (int w = 0; w < NTHREADS / 32; w++) S += ws[w];
        out[tid * UU + u] = S - diag[0] + diag[1 + tid] + bias[u];
    }
}

extern "C" void kernel_launch(void* const* d_in, const int* in_sizes, int n_in,
                              void* d_out, int out_size)
{
    const float* inputs = (const float*)d_in[0];  // (16, 2048)
    const float* matrix = (const float*)d_in[1];  // (2048, 2048)
    const float* weight = (const float*)d_in[2];  // (37, 2048, 2048)
    const float* bias   = (const float*)d_in[3];  // (37,)
    float* out = (float*)d_out;                    // (16, 37)

    gfrm_partial_kernel<<<NCHUNK + GBLOCKS, NTHREADS>>>(inputs, matrix, weight);

    // Dependent launch with programmatic stream serialization (PDL).
    cudaLaunchConfig_t cfg = {};
    cfg.gridDim  = dim3(UU);
    cfg.blockDim = dim3(NTHREADS);
    cfg.dynamicSmemBytes = 0;
    cfg.stream = 0;
    cudaLaunchAttribute attr[1];
    attr[0].id = cudaLaunchAttributeProgrammaticStreamSerialization;
    attr[0].val.programmaticStreamSerializationAllowed = 1;
    cfg.attrs = attr;
    cfg.numAttrs = 1;
    cudaLaunchKernelEx(&cfg, gfrm_final_kernel, (const float*)bias, (float*)out);
}